// round 1
// baseline (speedup 1.0000x reference)
#include <cuda_runtime.h>
#include <math.h>
#include <cfloat>

// ---------------- problem constants ----------------
#define Bv 8
#define Sv 256
#define Cv 4
#define Lv 256
#define Ev 256
#define Hv 8
#define DHv 32
#define ROWS (Bv*Sv)          // 2048

// ---------------- scratch (device globals; no cudaMalloc allowed) ----------------
__device__ float g_cnn[ROWS*Ev];
__device__ float g_feat[ROWS*Ev];
__device__ float g_h[ROWS*Ev];
__device__ float g_hn[ROWS*Ev];
__device__ float g_q[ROWS*Ev];
__device__ float g_k[ROWS*Ev];
__device__ float g_v[ROWS*Ev];
__device__ float g_attno[ROWS*Ev];
__device__ float g_ffn[ROWS*2*Ev];
__device__ float g_dist[Bv*Sv*Sv];
__device__ float g_scores[Bv*Hv*Sv*Sv];
__device__ float g_pooled[Bv*8*Ev];
__device__ unsigned g_dmax;

// ---------------- helpers ----------------
__device__ __forceinline__ float warpSum(float v) {
    #pragma unroll
    for (int o = 16; o > 0; o >>= 1) v += __shfl_xor_sync(0xFFFFFFFFu, v, o);
    return v;
}
__device__ __forceinline__ float warpMax(float v) {
    #pragma unroll
    for (int o = 16; o > 0; o >>= 1) v = fmaxf(v, __shfl_xor_sync(0xFFFFFFFFu, v, o));
    return v;
}

// ---------------- init (reset global-max each replay) ----------------
__global__ void init_kernel() {
    if (threadIdx.x == 0) g_dmax = 0u;
}

// ---------------- fused per-segment CNN: conv1+relu -> conv2 -> maxpool(L) -> relu ----------------
// block = (s, b); 256 threads; dynamic smem partitioned below
#define CONV_SMEM_FLOATS (24576 + 32*68 + 4*258 + 1536 + 128 + 256 + 256)
#define CONV_SMEM_BYTES  (CONV_SMEM_FLOATS * 4)

__global__ __launch_bounds__(256) void conv_fused_kernel(
    const float* __restrict__ x,  const float* __restrict__ w1,
    const float* __restrict__ b1, const float* __restrict__ w2,
    const float* __restrict__ b2)
{
    extern __shared__ float sm[];
    float* w2s  = sm;                    // [32 c][3 k][256 e] = 24576
    float* h1s  = w2s + 24576;           // [32 c][stride 68]  = 2176
    float* xs   = h1s + 2176;            // [4 ci][258]        = 1032
    float* w1s  = xs  + 1032;            // [128][12]          = 1536
    float* b1s  = w1s + 1536;            // 128
    float* b2s  = b1s + 128;             // 256
    float* mred = b2s + 256;             // 256

    const int t = threadIdx.x;
    const int s = blockIdx.x >> 3;
    const int b = blockIdx.x & 7;

    // stage x[b,s] with zero padding (index p = l+1)
    for (int idx = t; idx < 4*258; idx += 256) {
        int ci = idx / 258, p = idx - ci*258;
        float v = 0.f;
        if (p >= 1 && p <= 256) v = x[((b*Sv + s)*Cv + ci)*Lv + (p - 1)];
        xs[idx] = v;
    }
    for (int idx = t; idx < 1536; idx += 256) w1s[idx] = w1[s*1536 + idx];
    if (t < 128) b1s[t] = b1[s*128 + t];
    b2s[t] = b2[s*256 + t];

    const int et = t & 63;     // e group
    const int lt = t >> 6;     // l group (0..3)
    const int e0 = et * 4;
    const int lts = lt * 16;

    float m[4];
    #pragma unroll
    for (int j = 0; j < 4; j++) m[j] = -FLT_MAX;

    for (int lc = 0; lc < 4; lc++) {            // 64 l per chunk
        const int l0 = lc * 64;
        float acc[4][16];
        #pragma unroll
        for (int j = 0; j < 4; j++)
            #pragma unroll
            for (int ll = 0; ll < 16; ll++) acc[j][ll] = 0.f;

        for (int cc = 0; cc < 4; cc++) {        // 32 c per chunk
            __syncthreads();                     // protect h1s/w2s reuse
            // build h1 (conv1+relu) for this (c-chunk, l-window incl. halo)
            for (int idx = t; idx < 32*66; idx += 256) {
                int c = idx / 66, i = idx - c*66;
                int l = l0 - 1 + i;
                float v = 0.f;
                if (l >= 0 && l < 256) {
                    int cg = cc*32 + c;
                    float a = b1s[cg];
                    const float* wr = &w1s[cg*12];
                    #pragma unroll
                    for (int ci = 0; ci < 4; ci++) {
                        const float* xr = &xs[ci*258 + l];
                        a = fmaf(xr[0], wr[ci*3+0], a);
                        a = fmaf(xr[1], wr[ci*3+1], a);
                        a = fmaf(xr[2], wr[ci*3+2], a);
                    }
                    v = fmaxf(a, 0.f);
                }
                h1s[c*68 + i] = v;
            }
            // stage w2 chunk: global [s][e][c][k] -> smem [c][k][e]
            {
                const float4* src = (const float4*)(w2 + ((size_t)s*256 + t)*384 + cc*96);
                #pragma unroll
                for (int q = 0; q < 24; q++) {
                    float4 v4 = src[q];
                    w2s[(q*4+0)*256 + t] = v4.x;
                    w2s[(q*4+1)*256 + t] = v4.y;
                    w2s[(q*4+2)*256 + t] = v4.z;
                    w2s[(q*4+3)*256 + t] = v4.w;
                }
            }
            __syncthreads();
            // accumulate conv2
            for (int c = 0; c < 32; c++) {
                float hv[18];
                #pragma unroll
                for (int i = 0; i < 18; i++) hv[i] = h1s[c*68 + lts + i];
                const float* wp = &w2s[c*768 + e0];
                #pragma unroll
                for (int k = 0; k < 3; k++) {
                    float4 w4 = *(const float4*)(wp + k*256);
                    #pragma unroll
                    for (int ll = 0; ll < 16; ll++) {
                        float hvv = hv[ll + k];
                        acc[0][ll] = fmaf(hvv, w4.x, acc[0][ll]);
                        acc[1][ll] = fmaf(hvv, w4.y, acc[1][ll]);
                        acc[2][ll] = fmaf(hvv, w4.z, acc[2][ll]);
                        acc[3][ll] = fmaf(hvv, w4.w, acc[3][ll]);
                    }
                }
            }
        }
        // fold into running max over l
        #pragma unroll
        for (int j = 0; j < 4; j++)
            #pragma unroll
            for (int ll = 0; ll < 16; ll++) m[j] = fmaxf(m[j], acc[j][ll]);
    }

    // reduce max across the 4 l-groups
    for (int g = 0; g < 4; g++) {
        if (lt == g) {
            if (g == 0) {
                #pragma unroll
                for (int j = 0; j < 4; j++) mred[e0 + j] = m[j];
            } else {
                #pragma unroll
                for (int j = 0; j < 4; j++) mred[e0 + j] = fmaxf(mred[e0 + j], m[j]);
            }
        }
        __syncthreads();
    }
    // max over l of relu(z) == relu(max z); bias const over l
    g_cnn[(b*Sv + s)*Ev + t] = fmaxf(mred[t] + b2s[t], 0.f);
}

// ---------------- layernorm over E=256 (optional affine, optional duplicate output) ----------------
__global__ __launch_bounds__(256) void layernorm_kernel(
    const float* __restrict__ in, const float* __restrict__ gw,
    const float* __restrict__ bw, float* __restrict__ out, float* __restrict__ out2)
{
    int row = blockIdx.x, t = threadIdx.x;
    float v = in[row*256 + t];
    __shared__ float red[8];
    float s = warpSum(v);
    if ((t & 31) == 0) red[t >> 5] = s;
    __syncthreads();
    float tot = 0.f;
    #pragma unroll
    for (int i = 0; i < 8; i++) tot += red[i];
    float mean = tot * (1.f/256.f);
    float d = v - mean;
    __syncthreads();
    float s2 = warpSum(d * d);
    if ((t & 31) == 0) red[t >> 5] = s2;
    __syncthreads();
    float tot2 = 0.f;
    #pragma unroll
    for (int i = 0; i < 8; i++) tot2 += red[i];
    float y = d * rsqrtf(tot2 * (1.f/256.f) + 1e-5f);
    if (gw) y = y * gw[t] + bw[t];
    out[row*256 + t] = y;
    if (out2) out2[row*256 + t] = y;
}

// ---------------- pairwise distance + global max ----------------
__global__ __launch_bounds__(256) void dist_kernel(const float* __restrict__ feat)
{
    int bi = blockIdx.x;               // b*256 + i
    int b = bi >> 8, i = bi & 255;
    int t = threadIdx.x;               // j
    __shared__ float fi[256];
    __shared__ float red[8];
    fi[t] = feat[(b*256 + i)*256 + t];
    __syncthreads();
    const float4* f4 = (const float4*)fi;
    const float4* fj = (const float4*)(feat + (size_t)(b*256 + t)*256);
    float d2 = 0.f;
    #pragma unroll 8
    for (int q = 0; q < 64; q++) {
        float4 a = f4[q]; float4 c = fj[q];
        float dx = a.x - c.x, dy = a.y - c.y, dz = a.z - c.z, dw = a.w - c.w;
        d2 = fmaf(dx, dx, d2); d2 = fmaf(dy, dy, d2);
        d2 = fmaf(dz, dz, d2); d2 = fmaf(dw, dw, d2);
    }
    float dv = sqrtf(d2);
    g_dist[(size_t)bi*256 + t] = dv;
    float mx = warpMax(dv);
    if ((t & 31) == 0) red[t >> 5] = mx;
    __syncthreads();
    if (t == 0) {
        float mm = red[0];
        #pragma unroll
        for (int p = 1; p < 8; p++) mm = fmaxf(mm, red[p]);
        atomicMax(&g_dmax, __float_as_uint(mm));  // values >= 0: uint order == float order
    }
}

// ---------------- generic SGEMM: C = A[M,K]@B[K,N] (+bias, +residual, relu) ----------------
__global__ __launch_bounds__(256) void gemm_kernel(
    int M, int N, int K,
    const float* __restrict__ A, const float* __restrict__ Bm,
    const float* __restrict__ bias, const float* __restrict__ res,
    float* __restrict__ Cout, int relu)
{
    __shared__ float As[16][65];
    __shared__ float Bs[16][64];
    int t = threadIdx.x;
    int tn = t & 15, tm = t >> 4;
    int n0 = blockIdx.x << 6, m0 = blockIdx.y << 6;
    float acc[4][4];
    #pragma unroll
    for (int i = 0; i < 4; i++)
        #pragma unroll
        for (int j = 0; j < 4; j++) acc[i][j] = 0.f;

    for (int kk = 0; kk < K; kk += 16) {
        #pragma unroll
        for (int i = 0; i < 4; i++) {
            int lin = t + i*256;
            int am = lin >> 4, ak = lin & 15;
            As[ak][am] = A[(size_t)(m0 + am)*K + kk + ak];
            int bn = lin & 63, bk = lin >> 6;
            Bs[bk][bn] = Bm[(size_t)(kk + bk)*N + n0 + bn];
        }
        __syncthreads();
        #pragma unroll
        for (int k = 0; k < 16; k++) {
            float av[4], bv[4];
            #pragma unroll
            for (int j = 0; j < 4; j++) { av[j] = As[k][tm*4 + j]; bv[j] = Bs[k][tn*4 + j]; }
            #pragma unroll
            for (int i = 0; i < 4; i++)
                #pragma unroll
                for (int j = 0; j < 4; j++)
                    acc[i][j] = fmaf(av[i], bv[j], acc[i][j]);
        }
        __syncthreads();
    }
    #pragma unroll
    for (int i = 0; i < 4; i++) {
        int mrow = m0 + tm*4 + i;
        #pragma unroll
        for (int j = 0; j < 4; j++) {
            int n = n0 + tn*4 + j;
            float v = acc[i][j];
            if (bias) v += bias[n];
            if (res)  v += res[(size_t)mrow*N + n];
            if (relu) v = fmaxf(v, 0.f);
            Cout[(size_t)mrow*N + n] = v;
        }
    }
}

// ---------------- attention scores + bias + softmax ----------------
__global__ __launch_bounds__(256) void score_kernel(
    const float* __restrict__ q, const float* __restrict__ k,
    const float* __restrict__ bw, const float* __restrict__ bb)
{
    int blk = blockIdx.x;                 // ((b*8+h)*256 + i)
    int i = blk & 255, bh = blk >> 8;
    int h = bh & 7, b = bh >> 3;
    int j = threadIdx.x;
    __shared__ float qs[32];
    __shared__ float red[8];
    if (j < 32) qs[j] = q[((b*256 + i)*8 + h)*32 + j];
    __syncthreads();
    const float4* q4 = (const float4*)qs;
    const float4* k4 = (const float4*)(k + ((size_t)(b*256 + j)*8 + h)*32);
    float sc = 0.f;
    #pragma unroll
    for (int p = 0; p < 8; p++) {
        float4 a = q4[p], c = k4[p];
        sc = fmaf(a.x, c.x, sc); sc = fmaf(a.y, c.y, sc);
        sc = fmaf(a.z, c.z, sc); sc = fmaf(a.w, c.w, sc);
    }
    sc *= 0.17677669529663687f;           // 1/sqrt(32)
    float dmax = __uint_as_float(g_dmax);
    float dn = g_dist[(size_t)(b*256 + i)*256 + j] / (dmax + 1e-6f);
    float rd = fabsf((float)(i - j)) * (1.0f/255.0f);
    sc += dn*bw[h] + rd*bw[8+h] + (1.f - rd)*bw[16+h] + (1.f - dn)*bw[24+h] + bb[h];
    // softmax over j
    float mx = warpMax(sc);
    if ((j & 31) == 0) red[j >> 5] = mx;
    __syncthreads();
    float bm = red[0];
    #pragma unroll
    for (int p = 1; p < 8; p++) bm = fmaxf(bm, red[p]);
    float e = expf(sc - bm);
    __syncthreads();
    float s = warpSum(e);
    if ((j & 31) == 0) red[j >> 5] = s;
    __syncthreads();
    float tot = 0.f;
    #pragma unroll
    for (int p = 0; p < 8; p++) tot += red[p];
    g_scores[(size_t)blk*256 + j] = e / tot;
}

// ---------------- attention output: o = A @ V ----------------
__global__ __launch_bounds__(256) void av_kernel(const float* __restrict__ v)
{
    int bi = blockIdx.x;                  // b*256 + i
    int b = bi >> 8, i = bi & 255;
    int t = threadIdx.x;
    int h = t >> 5, d = t & 31;
    __shared__ float as_[8*256];
    for (int idx = t; idx < 2048; idx += 256) {
        int hh = idx >> 8, j = idx & 255;
        as_[idx] = g_scores[((size_t)((b*8 + hh)*256 + i))*256 + j];
    }
    __syncthreads();
    float acc = 0.f;
    #pragma unroll 4
    for (int j = 0; j < 256; j++)
        acc = fmaf(as_[h*256 + j], v[(size_t)(b*256 + j)*256 + h*32 + d], acc);
    g_attno[(size_t)(b*256 + i)*256 + t] = acc;
}

// ---------------- segment max pool ----------------
__global__ __launch_bounds__(256) void pool_kernel()
{
    int blk = blockIdx.x;                 // b*8 + ns
    int b = blk >> 3, ns = blk & 7;
    int t = threadIdx.x;
    float mx = -FLT_MAX;
    #pragma unroll 4
    for (int si = 0; si < 32; si++)
        mx = fmaxf(mx, g_h[(size_t)(b*256 + ns*32 + si)*256 + t]);
    g_pooled[b*2048 + ns*256 + t] = mx;
}

// ---------------- final FC [8,2048] x [2048,2] ----------------
__global__ __launch_bounds__(256) void fc_kernel(
    const float* __restrict__ fw, const float* __restrict__ fb, float* __restrict__ out)
{
    int b = blockIdx.x, t = threadIdx.x;
    float a0 = 0.f, a1 = 0.f;
    for (int kk = t; kk < 2048; kk += 256) {
        float p = g_pooled[b*2048 + kk];
        a0 = fmaf(p, fw[kk*2 + 0], a0);
        a1 = fmaf(p, fw[kk*2 + 1], a1);
    }
    __shared__ float r0[8], r1[8];
    a0 = warpSum(a0); a1 = warpSum(a1);
    if ((t & 31) == 0) { r0[t >> 5] = a0; r1[t >> 5] = a1; }
    __syncthreads();
    if (t == 0) {
        float s0 = 0.f, s1 = 0.f;
        #pragma unroll
        for (int p = 0; p < 8; p++) { s0 += r0[p]; s1 += r1[p]; }
        out[b*2 + 0] = s0 + fb[0];
        out[b*2 + 1] = s1 + fb[1];
    }
}

// ---------------- launch ----------------
extern "C" void kernel_launch(void* const* d_in, const int* in_sizes, int n_in,
                              void* d_out, int out_size)
{
    const float* x       = (const float*)d_in[0];
    const float* conv1_w = (const float*)d_in[1];
    const float* conv1_b = (const float*)d_in[2];
    const float* conv2_w = (const float*)d_in[3];
    const float* conv2_b = (const float*)d_in[4];
    const float* ln1_g   = (const float*)d_in[5];
    const float* ln1_b   = (const float*)d_in[6];
    const float* wq      = (const float*)d_in[7];
    const float* bq      = (const float*)d_in[8];
    const float* wk      = (const float*)d_in[9];
    const float* bk      = (const float*)d_in[10];
    const float* wv      = (const float*)d_in[11];
    const float* bv      = (const float*)d_in[12];
    const float* wo      = (const float*)d_in[13];
    const float* bo      = (const float*)d_in[14];
    const float* bias_w  = (const float*)d_in[15];
    const float* bias_b  = (const float*)d_in[16];
    const float* ln2_g   = (const float*)d_in[17];
    const float* ln2_b   = (const float*)d_in[18];
    const float* ffn_w1  = (const float*)d_in[19];
    const float* ffn_b1  = (const float*)d_in[20];
    const float* ffn_w2  = (const float*)d_in[21];
    const float* ffn_b2  = (const float*)d_in[22];
    const float* fc_w    = (const float*)d_in[23];
    const float* fc_b    = (const float*)d_in[24];
    float* out = (float*)d_out;

    float *p_cnn, *p_feat, *p_h, *p_hn, *p_q, *p_k, *p_v, *p_attno, *p_ffn;
    cudaGetSymbolAddress((void**)&p_cnn,   g_cnn);
    cudaGetSymbolAddress((void**)&p_feat,  g_feat);
    cudaGetSymbolAddress((void**)&p_h,     g_h);
    cudaGetSymbolAddress((void**)&p_hn,    g_hn);
    cudaGetSymbolAddress((void**)&p_q,     g_q);
    cudaGetSymbolAddress((void**)&p_k,     g_k);
    cudaGetSymbolAddress((void**)&p_v,     g_v);
    cudaGetSymbolAddress((void**)&p_attno, g_attno);
    cudaGetSymbolAddress((void**)&p_ffn,   g_ffn);

    cudaFuncSetAttribute(conv_fused_kernel,
                         cudaFuncAttributeMaxDynamicSharedMemorySize, CONV_SMEM_BYTES);

    init_kernel<<<1, 32>>>();
    conv_fused_kernel<<<2048, 256, CONV_SMEM_BYTES>>>(x, conv1_w, conv1_b, conv2_w, conv2_b);
    // feat = LN(cnn) (no affine); h starts as feat
    layernorm_kernel<<<ROWS, 256>>>(p_cnn, nullptr, nullptr, p_feat, p_h);
    dist_kernel<<<ROWS, 256>>>(p_feat);

    dim3 g256(4, 32);   // N=256
    dim3 g512(8, 32);   // N=512
    for (int l = 0; l < 2; l++) {
        layernorm_kernel<<<ROWS, 256>>>(p_h, ln1_g + l*256, ln1_b + l*256, p_hn, nullptr);
        gemm_kernel<<<g256, 256>>>(ROWS, 256, 256, p_hn, wq + l*65536, bq + l*256, nullptr, p_q, 0);
        gemm_kernel<<<g256, 256>>>(ROWS, 256, 256, p_hn, wk + l*65536, bk + l*256, nullptr, p_k, 0);
        gemm_kernel<<<g256, 256>>>(ROWS, 256, 256, p_hn, wv + l*65536, bv + l*256, nullptr, p_v, 0);
        score_kernel<<<Bv*Hv*Sv, 256>>>(p_q, p_k, bias_w + l*32, bias_b + l*8);
        av_kernel<<<ROWS, 256>>>(p_v);
        gemm_kernel<<<g256, 256>>>(ROWS, 256, 256, p_attno, wo + l*65536, bo + l*256, p_h, p_h, 0);
        layernorm_kernel<<<ROWS, 256>>>(p_h, ln2_g + l*256, ln2_b + l*256, p_hn, nullptr);
        gemm_kernel<<<g512, 256>>>(ROWS, 512, 256, p_hn, ffn_w1 + l*131072, ffn_b1 + l*512, nullptr, p_ffn, 1);
        gemm_kernel<<<g256, 256>>>(ROWS, 256, 512, p_ffn, ffn_w2 + l*131072, ffn_b2 + l*256, p_h, p_h, 0);
    }

    pool_kernel<<<64, 256>>>();
    fc_kernel<<<8, 256>>>(fc_w, fc_b, out);
}

// round 2
// speedup vs baseline: 1.0793x; 1.0793x over previous
#include <cuda_runtime.h>
#include <math.h>
#include <cfloat>

// ---------------- problem constants ----------------
#define Bv 8
#define Sv 256
#define Cv 4
#define Lv 256
#define Ev 256
#define Hv 8
#define DHv 32
#define ROWS (Bv*Sv)          // 2048

// ---------------- scratch (device globals; no cudaMalloc allowed) ----------------
__device__ float g_cnn[ROWS*Ev];
__device__ float g_feat[ROWS*Ev];
__device__ float g_h[ROWS*Ev];
__device__ float g_hn[ROWS*Ev];
__device__ float g_q[ROWS*Ev];
__device__ float g_k[ROWS*Ev];
__device__ float g_v[ROWS*Ev];
__device__ float g_attno[ROWS*Ev];
__device__ float g_ffn[ROWS*2*Ev];
__device__ float g_dist[Bv*Sv*Sv];
__device__ float g_scores[Bv*Hv*Sv*Sv];
__device__ float g_pooled[Bv*8*Ev];
__device__ unsigned g_dmax;

// ---------------- helpers ----------------
__device__ __forceinline__ float warpSum(float v) {
    #pragma unroll
    for (int o = 16; o > 0; o >>= 1) v += __shfl_xor_sync(0xFFFFFFFFu, v, o);
    return v;
}
__device__ __forceinline__ float warpMax(float v) {
    #pragma unroll
    for (int o = 16; o > 0; o >>= 1) v = fmaxf(v, __shfl_xor_sync(0xFFFFFFFFu, v, o));
    return v;
}

// ---------------- init (reset global-max each replay) ----------------
__global__ void init_kernel() {
    if (threadIdx.x == 0) g_dmax = 0u;
}

// ---------------- fused per-segment CNN: conv1+relu -> conv2 -> maxpool(L) -> relu ----------------
// block = (s, b); 256 threads; dynamic smem partitioned below
#define CONV_SMEM_FLOATS (24576 + 32*68 + 4*258 + 1536 + 128 + 256 + 256)
#define CONV_SMEM_BYTES  (CONV_SMEM_FLOATS * 4)

__global__ __launch_bounds__(256) void conv_fused_kernel(
    const float* __restrict__ x,  const float* __restrict__ w1,
    const float* __restrict__ b1, const float* __restrict__ w2,
    const float* __restrict__ b2)
{
    extern __shared__ float sm[];
    float* w2s  = sm;                    // [32 c][3 k][256 e] = 24576
    float* h1s  = w2s + 24576;           // [32 c][stride 68]  = 2176
    float* xs   = h1s + 2176;            // [4 ci][258]        = 1032
    float* w1s  = xs  + 1032;            // [128][12]          = 1536
    float* b1s  = w1s + 1536;            // 128
    float* b2s  = b1s + 128;             // 256
    float* mred = b2s + 256;             // 256

    const int t = threadIdx.x;
    const int s = blockIdx.x >> 3;
    const int b = blockIdx.x & 7;

    // stage x[b,s] with zero padding (index p = l+1)
    for (int idx = t; idx < 4*258; idx += 256) {
        int ci = idx / 258, p = idx - ci*258;
        float v = 0.f;
        if (p >= 1 && p <= 256) v = x[((b*Sv + s)*Cv + ci)*Lv + (p - 1)];
        xs[idx] = v;
    }
    for (int idx = t; idx < 1536; idx += 256) w1s[idx] = w1[s*1536 + idx];
    if (t < 128) b1s[t] = b1[s*128 + t];
    b2s[t] = b2[s*256 + t];

    const int et = t & 63;     // e group
    const int lt = t >> 6;     // l group (0..3)
    const int e0 = et * 4;
    const int lts = lt * 16;

    float m[4];
    #pragma unroll
    for (int j = 0; j < 4; j++) m[j] = -FLT_MAX;

    for (int lc = 0; lc < 4; lc++) {            // 64 l per chunk
        const int l0 = lc * 64;
        float acc[4][16];
        #pragma unroll
        for (int j = 0; j < 4; j++)
            #pragma unroll
            for (int ll = 0; ll < 16; ll++) acc[j][ll] = 0.f;

        for (int cc = 0; cc < 4; cc++) {        // 32 c per chunk
            __syncthreads();                     // protect h1s/w2s reuse
            // build h1 (conv1+relu) for this (c-chunk, l-window incl. halo)
            for (int idx = t; idx < 32*66; idx += 256) {
                int c = idx / 66, i = idx - c*66;
                int l = l0 - 1 + i;
                float v = 0.f;
                if (l >= 0 && l < 256) {
                    int cg = cc*32 + c;
                    float a = b1s[cg];
                    const float* wr = &w1s[cg*12];
                    #pragma unroll
                    for (int ci = 0; ci < 4; ci++) {
                        const float* xr = &xs[ci*258 + l];
                        a = fmaf(xr[0], wr[ci*3+0], a);
                        a = fmaf(xr[1], wr[ci*3+1], a);
                        a = fmaf(xr[2], wr[ci*3+2], a);
                    }
                    v = fmaxf(a, 0.f);
                }
                h1s[c*68 + i] = v;
            }
            // stage w2 chunk: global [s][e][c][k] -> smem [c][k][e]
            {
                const float4* src = (const float4*)(w2 + ((size_t)s*256 + t)*384 + cc*96);
                #pragma unroll
                for (int q = 0; q < 24; q++) {
                    float4 v4 = src[q];
                    w2s[(q*4+0)*256 + t] = v4.x;
                    w2s[(q*4+1)*256 + t] = v4.y;
                    w2s[(q*4+2)*256 + t] = v4.z;
                    w2s[(q*4+3)*256 + t] = v4.w;
                }
            }
            __syncthreads();
            // accumulate conv2
            for (int c = 0; c < 32; c++) {
                float hv[18];
                #pragma unroll
                for (int i = 0; i < 18; i++) hv[i] = h1s[c*68 + lts + i];
                const float* wp = &w2s[c*768 + e0];
                #pragma unroll
                for (int k = 0; k < 3; k++) {
                    float4 w4 = *(const float4*)(wp + k*256);
                    #pragma unroll
                    for (int ll = 0; ll < 16; ll++) {
                        float hvv = hv[ll + k];
                        acc[0][ll] = fmaf(hvv, w4.x, acc[0][ll]);
                        acc[1][ll] = fmaf(hvv, w4.y, acc[1][ll]);
                        acc[2][ll] = fmaf(hvv, w4.z, acc[2][ll]);
                        acc[3][ll] = fmaf(hvv, w4.w, acc[3][ll]);
                    }
                }
            }
        }
        // fold into running max over l
        #pragma unroll
        for (int j = 0; j < 4; j++)
            #pragma unroll
            for (int ll = 0; ll < 16; ll++) m[j] = fmaxf(m[j], acc[j][ll]);
    }

    // reduce max across the 4 l-groups
    for (int g = 0; g < 4; g++) {
        if (lt == g) {
            if (g == 0) {
                #pragma unroll
                for (int j = 0; j < 4; j++) mred[e0 + j] = m[j];
            } else {
                #pragma unroll
                for (int j = 0; j < 4; j++) mred[e0 + j] = fmaxf(mred[e0 + j], m[j]);
            }
        }
        __syncthreads();
    }
    // max over l of relu(z) == relu(max z); bias const over l
    g_cnn[(b*Sv + s)*Ev + t] = fmaxf(mred[t] + b2s[t], 0.f);
}

// ---------------- layernorm over E=256 (optional affine, optional duplicate output) ----------------
__global__ __launch_bounds__(256) void layernorm_kernel(
    const float* __restrict__ in, const float* __restrict__ gw,
    const float* __restrict__ bw, float* __restrict__ out, float* __restrict__ out2)
{
    int row = blockIdx.x, t = threadIdx.x;
    float v = in[row*256 + t];
    __shared__ float red[8];
    float s = warpSum(v);
    if ((t & 31) == 0) red[t >> 5] = s;
    __syncthreads();
    float tot = 0.f;
    #pragma unroll
    for (int i = 0; i < 8; i++) tot += red[i];
    float mean = tot * (1.f/256.f);
    float d = v - mean;
    __syncthreads();
    float s2 = warpSum(d * d);
    if ((t & 31) == 0) red[t >> 5] = s2;
    __syncthreads();
    float tot2 = 0.f;
    #pragma unroll
    for (int i = 0; i < 8; i++) tot2 += red[i];
    float y = d * rsqrtf(tot2 * (1.f/256.f) + 1e-5f);
    if (gw) y = y * gw[t] + bw[t];
    out[row*256 + t] = y;
    if (out2) out2[row*256 + t] = y;
}

// ---------------- pairwise distance + global max ----------------
__global__ __launch_bounds__(256) void dist_kernel(const float* __restrict__ feat)
{
    int bi = blockIdx.x;               // b*256 + i
    int b = bi >> 8, i = bi & 255;
    int t = threadIdx.x;               // j
    __shared__ float fi[256];
    __shared__ float red[8];
    fi[t] = feat[(b*256 + i)*256 + t];
    __syncthreads();
    const float4* f4 = (const float4*)fi;
    const float4* fj = (const float4*)(feat + (size_t)(b*256 + t)*256);
    float d2 = 0.f;
    #pragma unroll 8
    for (int q = 0; q < 64; q++) {
        float4 a = f4[q]; float4 c = fj[q];
        float dx = a.x - c.x, dy = a.y - c.y, dz = a.z - c.z, dw = a.w - c.w;
        d2 = fmaf(dx, dx, d2); d2 = fmaf(dy, dy, d2);
        d2 = fmaf(dz, dz, d2); d2 = fmaf(dw, dw, d2);
    }
    float dv = sqrtf(d2);
    g_dist[(size_t)bi*256 + t] = dv;
    float mx = warpMax(dv);
    if ((t & 31) == 0) red[t >> 5] = mx;
    __syncthreads();
    if (t == 0) {
        float mm = red[0];
        #pragma unroll
        for (int p = 1; p < 8; p++) mm = fmaxf(mm, red[p]);
        atomicMax(&g_dmax, __float_as_uint(mm));  // values >= 0: uint order == float order
    }
}

// ---------------- generic SGEMM: C = A[M,K]@B[K,N] (+bias, +residual, relu) ----------------
__global__ __launch_bounds__(256) void gemm_kernel(
    int M, int N, int K,
    const float* __restrict__ A, const float* __restrict__ Bm,
    const float* __restrict__ bias, const float* __restrict__ res,
    float* __restrict__ Cout, int relu)
{
    __shared__ float As[16][65];
    __shared__ float Bs[16][64];
    int t = threadIdx.x;
    int tn = t & 15, tm = t >> 4;
    int n0 = blockIdx.x << 6, m0 = blockIdx.y << 6;
    float acc[4][4];
    #pragma unroll
    for (int i = 0; i < 4; i++)
        #pragma unroll
        for (int j = 0; j < 4; j++) acc[i][j] = 0.f;

    for (int kk = 0; kk < K; kk += 16) {
        #pragma unroll
        for (int i = 0; i < 4; i++) {
            int lin = t + i*256;
            int am = lin >> 4, ak = lin & 15;
            As[ak][am] = A[(size_t)(m0 + am)*K + kk + ak];
            int bn = lin & 63, bk = lin >> 6;
            Bs[bk][bn] = Bm[(size_t)(kk + bk)*N + n0 + bn];
        }
        __syncthreads();
        #pragma unroll
        for (int k = 0; k < 16; k++) {
            float av[4], bv[4];
            #pragma unroll
            for (int j = 0; j < 4; j++) { av[j] = As[k][tm*4 + j]; bv[j] = Bs[k][tn*4 + j]; }
            #pragma unroll
            for (int i = 0; i < 4; i++)
                #pragma unroll
                for (int j = 0; j < 4; j++)
                    acc[i][j] = fmaf(av[i], bv[j], acc[i][j]);
        }
        __syncthreads();
    }
    #pragma unroll
    for (int i = 0; i < 4; i++) {
        int mrow = m0 + tm*4 + i;
        #pragma unroll
        for (int j = 0; j < 4; j++) {
            int n = n0 + tn*4 + j;
            float v = acc[i][j];
            if (bias) v += bias[n];
            if (res)  v += res[(size_t)mrow*N + n];
            if (relu) v = fmaxf(v, 0.f);
            Cout[(size_t)mrow*N + n] = v;
        }
    }
}

// ---------------- attention scores + bias + softmax ----------------
__global__ __launch_bounds__(256) void score_kernel(
    const float* __restrict__ q, const float* __restrict__ k,
    const float* __restrict__ bw, const float* __restrict__ bb)
{
    int blk = blockIdx.x;                 // ((b*8+h)*256 + i)
    int i = blk & 255, bh = blk >> 8;
    int h = bh & 7, b = bh >> 3;
    int j = threadIdx.x;
    __shared__ float qs[32];
    __shared__ float red[8];
    if (j < 32) qs[j] = q[((b*256 + i)*8 + h)*32 + j];
    __syncthreads();
    const float4* q4 = (const float4*)qs;
    const float4* k4 = (const float4*)(k + ((size_t)(b*256 + j)*8 + h)*32);
    float sc = 0.f;
    #pragma unroll
    for (int p = 0; p < 8; p++) {
        float4 a = q4[p], c = k4[p];
        sc = fmaf(a.x, c.x, sc); sc = fmaf(a.y, c.y, sc);
        sc = fmaf(a.z, c.z, sc); sc = fmaf(a.w, c.w, sc);
    }
    sc *= 0.17677669529663687f;           // 1/sqrt(32)
    float dmax = __uint_as_float(g_dmax);
    float dn = g_dist[(size_t)(b*256 + i)*256 + j] / (dmax + 1e-6f);
    float rd = fabsf((float)(i - j)) * (1.0f/255.0f);
    sc += dn*bw[h] + rd*bw[8+h] + (1.f - rd)*bw[16+h] + (1.f - dn)*bw[24+h] + bb[h];
    // softmax over j
    float mx = warpMax(sc);
    if ((j & 31) == 0) red[j >> 5] = mx;
    __syncthreads();
    float bm = red[0];
    #pragma unroll
    for (int p = 1; p < 8; p++) bm = fmaxf(bm, red[p]);
    float e = expf(sc - bm);
    __syncthreads();
    float s = warpSum(e);
    if ((j & 31) == 0) red[j >> 5] = s;
    __syncthreads();
    float tot = 0.f;
    #pragma unroll
    for (int p = 0; p < 8; p++) tot += red[p];
    g_scores[(size_t)blk*256 + j] = e / tot;
}

// ---------------- attention output: o = A @ V ----------------
__global__ __launch_bounds__(256) void av_kernel(const float* __restrict__ v)
{
    int bi = blockIdx.x;                  // b*256 + i
    int b = bi >> 8, i = bi & 255;
    int t = threadIdx.x;
    int h = t >> 5, d = t & 31;
    __shared__ float as_[8*256];
    for (int idx = t; idx < 2048; idx += 256) {
        int hh = idx >> 8, j = idx & 255;
        as_[idx] = g_scores[((size_t)((b*8 + hh)*256 + i))*256 + j];
    }
    __syncthreads();
    float acc = 0.f;
    #pragma unroll 4
    for (int j = 0; j < 256; j++)
        acc = fmaf(as_[h*256 + j], v[(size_t)(b*256 + j)*256 + h*32 + d], acc);
    g_attno[(size_t)(b*256 + i)*256 + t] = acc;
}

// ---------------- segment max pool ----------------
__global__ __launch_bounds__(256) void pool_kernel()
{
    int blk = blockIdx.x;                 // b*8 + ns
    int b = blk >> 3, ns = blk & 7;
    int t = threadIdx.x;
    float mx = -FLT_MAX;
    #pragma unroll 4
    for (int si = 0; si < 32; si++)
        mx = fmaxf(mx, g_h[(size_t)(b*256 + ns*32 + si)*256 + t]);
    g_pooled[b*2048 + ns*256 + t] = mx;
}

// ---------------- final FC [8,2048] x [2048,2] ----------------
__global__ __launch_bounds__(256) void fc_kernel(
    const float* __restrict__ fw, const float* __restrict__ fb, float* __restrict__ out)
{
    int b = blockIdx.x, t = threadIdx.x;
    float a0 = 0.f, a1 = 0.f;
    for (int kk = t; kk < 2048; kk += 256) {
        float p = g_pooled[b*2048 + kk];
        a0 = fmaf(p, fw[kk*2 + 0], a0);
        a1 = fmaf(p, fw[kk*2 + 1], a1);
    }
    __shared__ float r0[8], r1[8];
    a0 = warpSum(a0); a1 = warpSum(a1);
    if ((t & 31) == 0) { r0[t >> 5] = a0; r1[t >> 5] = a1; }
    __syncthreads();
    if (t == 0) {
        float s0 = 0.f, s1 = 0.f;
        #pragma unroll
        for (int p = 0; p < 8; p++) { s0 += r0[p]; s1 += r1[p]; }
        out[b*2 + 0] = s0 + fb[0];
        out[b*2 + 1] = s1 + fb[1];
    }
}

// ---------------- launch ----------------
extern "C" void kernel_launch(void* const* d_in, const int* in_sizes, int n_in,
                              void* d_out, int out_size)
{
    const float* x       = (const float*)d_in[0];
    const float* conv1_w = (const float*)d_in[1];
    const float* conv1_b = (const float*)d_in[2];
    const float* conv2_w = (const float*)d_in[3];
    const float* conv2_b = (const float*)d_in[4];
    const float* ln1_g   = (const float*)d_in[5];
    const float* ln1_b   = (const float*)d_in[6];
    const float* wq      = (const float*)d_in[7];
    const float* bq      = (const float*)d_in[8];
    const float* wk      = (const float*)d_in[9];
    const float* bk      = (const float*)d_in[10];
    const float* wv      = (const float*)d_in[11];
    const float* bv      = (const float*)d_in[12];
    const float* wo      = (const float*)d_in[13];
    const float* bo      = (const float*)d_in[14];
    const float* bias_w  = (const float*)d_in[15];
    const float* bias_b  = (const float*)d_in[16];
    const float* ln2_g   = (const float*)d_in[17];
    const float* ln2_b   = (const float*)d_in[18];
    const float* ffn_w1  = (const float*)d_in[19];
    const float* ffn_b1  = (const float*)d_in[20];
    const float* ffn_w2  = (const float*)d_in[21];
    const float* ffn_b2  = (const float*)d_in[22];
    const float* fc_w    = (const float*)d_in[23];
    const float* fc_b    = (const float*)d_in[24];
    float* out = (float*)d_out;

    float *p_cnn, *p_feat, *p_h, *p_hn, *p_q, *p_k, *p_v, *p_attno, *p_ffn;
    cudaGetSymbolAddress((void**)&p_cnn,   g_cnn);
    cudaGetSymbolAddress((void**)&p_feat,  g_feat);
    cudaGetSymbolAddress((void**)&p_h,     g_h);
    cudaGetSymbolAddress((void**)&p_hn,    g_hn);
    cudaGetSymbolAddress((void**)&p_q,     g_q);
    cudaGetSymbolAddress((void**)&p_k,     g_k);
    cudaGetSymbolAddress((void**)&p_v,     g_v);
    cudaGetSymbolAddress((void**)&p_attno, g_attno);
    cudaGetSymbolAddress((void**)&p_ffn,   g_ffn);

    cudaFuncSetAttribute(conv_fused_kernel,
                         cudaFuncAttributeMaxDynamicSharedMemorySize, CONV_SMEM_BYTES);

    init_kernel<<<1, 32>>>();
    conv_fused_kernel<<<2048, 256, CONV_SMEM_BYTES>>>(x, conv1_w, conv1_b, conv2_w, conv2_b);
    // feat = LN(cnn) (no affine); h starts as feat
    layernorm_kernel<<<ROWS, 256>>>(p_cnn, nullptr, nullptr, p_feat, p_h);
    dist_kernel<<<ROWS, 256>>>(p_feat);

    dim3 g256(4, 32);   // N=256
    dim3 g512(8, 32);   // N=512
    for (int l = 0; l < 2; l++) {
        layernorm_kernel<<<ROWS, 256>>>(p_h, ln1_g + l*256, ln1_b + l*256, p_hn, nullptr);
        gemm_kernel<<<g256, 256>>>(ROWS, 256, 256, p_hn, wq + l*65536, bq + l*256, nullptr, p_q, 0);
        gemm_kernel<<<g256, 256>>>(ROWS, 256, 256, p_hn, wk + l*65536, bk + l*256, nullptr, p_k, 0);
        gemm_kernel<<<g256, 256>>>(ROWS, 256, 256, p_hn, wv + l*65536, bv + l*256, nullptr, p_v, 0);
        score_kernel<<<Bv*Hv*Sv, 256>>>(p_q, p_k, bias_w + l*32, bias_b + l*8);
        av_kernel<<<ROWS, 256>>>(p_v);
        gemm_kernel<<<g256, 256>>>(ROWS, 256, 256, p_attno, wo + l*65536, bo + l*256, p_h, p_h, 0);
        layernorm_kernel<<<ROWS, 256>>>(p_h, ln2_g + l*256, ln2_b + l*256, p_hn, nullptr);
        gemm_kernel<<<g512, 256>>>(ROWS, 512, 256, p_hn, ffn_w1 + l*131072, ffn_b1 + l*512, nullptr, p_ffn, 1);
        gemm_kernel<<<g256, 256>>>(ROWS, 256, 512, p_ffn, ffn_w2 + l*131072, ffn_b2 + l*256, p_h, p_h, 0);
    }

    pool_kernel<<<64, 256>>>();
    fc_kernel<<<8, 256>>>(fc_w, fc_b, out);
}

// round 4
// speedup vs baseline: 3.1100x; 2.8815x over previous
#include <cuda_runtime.h>
#include <math.h>
#include <cfloat>
#include <stdint.h>

#define Bv 8
#define Sv 256
#define Ev 256
#define Hv 8
#define ROWS (Bv*Sv)

__device__ float g_cnn[ROWS*Ev];
__device__ float g_feat[ROWS*Ev];
__device__ float g_h[ROWS*Ev];
__device__ float g_hn[ROWS*Ev];
__device__ float g_q[ROWS*Ev];
__device__ float g_k[ROWS*Ev];
__device__ float g_v[ROWS*Ev];
__device__ float g_attno[ROWS*Ev];
__device__ float g_ffn[ROWS*2*Ev];
__device__ float g_dist[Bv*Sv*Sv];
__device__ float g_scores[Bv*Hv*Sv*Sv];
__device__ float g_pooled[Bv*8*Ev];
__device__ float g_sq[ROWS];
__device__ unsigned g_dmax;
__device__ float g_h1p[(size_t)2048*128*264];   // conv1 out, tf32, padded rows
__device__ float g_w2t[(size_t)256*384*256];    // w2 transposed, tf32

__device__ __forceinline__ float warpSum(float v){
    #pragma unroll
    for(int o=16;o>0;o>>=1) v += __shfl_xor_sync(0xFFFFFFFFu,v,o);
    return v;
}
__device__ __forceinline__ float warpMax(float v){
    #pragma unroll
    for(int o=16;o>0;o>>=1) v = fmaxf(v,__shfl_xor_sync(0xFFFFFFFFu,v,o));
    return v;
}
__device__ __forceinline__ float ftf32(float x){
    unsigned u; asm("cvt.rna.tf32.f32 %0, %1;" : "=r"(u) : "f"(x));
    return __uint_as_float(u);
}
__device__ __forceinline__ void cpa16(void* sm, const void* g){
    unsigned sa = (unsigned)__cvta_generic_to_shared(sm);
    asm volatile("cp.async.cg.shared.global [%0], [%1], 16;" :: "r"(sa), "l"(g));
}
#define CP_COMMIT() asm volatile("cp.async.commit_group;")
#define CP_WAIT(N)  asm volatile("cp.async.wait_group %0;" :: "n"(N))
#define MMA_TF32(C,A,B) \
    asm volatile("mma.sync.aligned.m16n8k8.row.col.f32.tf32.tf32.f32 " \
        "{%0,%1,%2,%3},{%4,%5,%6,%7},{%8,%9},{%0,%1,%2,%3};" \
        : "+f"((C)[0]),"+f"((C)[1]),"+f"((C)[2]),"+f"((C)[3]) \
        : "r"((A)[0]),"r"((A)[1]),"r"((A)[2]),"r"((A)[3]),"r"((B)[0]),"r"((B)[1]))

__global__ void init_kernel(){ if(threadIdx.x==0) g_dmax=0u; }

// ---- conv1 -> g_h1p (tf32, rows of 264 with zero pads at p=0 and p>=257) ----
__global__ __launch_bounds__(256) void conv1_kernel(
    const float* __restrict__ x, const float* __restrict__ w1, const float* __restrict__ b1)
{
    __shared__ float xs[4*258], w1s[1536], b1s[128];
    int t=threadIdx.x, sb=blockIdx.x, s=sb>>3, b=sb&7;
    for(int idx=t; idx<4*258; idx+=256){
        int ci=idx/258, p=idx-ci*258; float v=0.f;
        if(p>=1 && p<=256) v = x[((b*Sv+s)*4+ci)*256 + p-1];
        xs[idx]=v;
    }
    for(int idx=t; idx<1536; idx+=256) w1s[idx]=w1[s*1536+idx];
    if(t<128) b1s[t]=b1[s*128+t];
    __syncthreads();
    for(int idx=t; idx<128*256; idx+=256){
        int c=idx>>8, lp=idx&255;
        float a=b1s[c]; const float* wr=&w1s[c*12];
        #pragma unroll
        for(int ci=0;ci<4;ci++){
            const float* xr=&xs[ci*258+lp];
            a=fmaf(xr[0],wr[ci*3+0],a); a=fmaf(xr[1],wr[ci*3+1],a); a=fmaf(xr[2],wr[ci*3+2],a);
        }
        g_h1p[((size_t)sb*128+c)*264 + lp+1] = ftf32(fmaxf(a,0.f));
    }
    for(int idx=t; idx<128*8; idx+=256){
        int c=idx>>3, q=idx&7, p=(q==0)?0:(256+q);
        g_h1p[((size_t)sb*128+c)*264 + p]=0.f;
    }
}

// ---- w2 transpose: [s][e][c*3+k] -> g_w2t[s][k*128+c][e] (tf32) ----
__global__ __launch_bounds__(256) void w2t_kernel(const float* __restrict__ w2)
{
    __shared__ float tile[64*97];
    int t=threadIdx.x, bx=blockIdx.x;
    int s=bx>>4, et=(bx>>2)&3, kt=bx&3;
    for(int idx=t; idx<64*96; idx+=256){
        int e=idx/96, sc=idx-e*96;
        tile[e*97+sc] = w2[((size_t)(s*256+et*64+e))*384 + kt*96 + sc];
    }
    __syncthreads();
    for(int idx=t; idx<64*96; idx+=256){
        int sc=idx>>6, e=idx&63;
        int cd=sc/3, c=kt*32+cd, k=sc-cd*3;
        g_w2t[((size_t)(s*384+k*128+c))*256 + et*64+e] = ftf32(tile[e*97+sc]);
    }
}

// ---- conv2 as tf32 MMA GEMM (M=128 e, N=256 l, K=384) + maxpool epilogue ----
#define ASW 136
#define BSW 264
#define A_WORDS (96*ASW)
#define STAGE_WORDS (A_WORDS + 32*BSW)
#define CONV2_SMEM_BYTES (2*STAGE_WORDS*4)

__global__ __launch_bounds__(256,1) void conv2_mma_kernel(const float* __restrict__ b2)
{
    extern __shared__ float smc[];
    int t=threadIdx.x, bx=blockIdx.x;
    int s=bx>>4, eh=(bx>>3)&1, b=bx&7, sb=s*8+b;
    int lane=t&31, wid=t>>5, gg=lane>>2, tg=lane&3;
    int wm=wid&1, wn=wid>>1, e0=eh*128;
    const float* Ag = g_w2t + (size_t)s*384*256 + e0;
    const float* Bg = g_h1p + (size_t)sb*128*264;

    float acc[4][8][4];
    #pragma unroll
    for(int i=0;i<4;i++)
        #pragma unroll
        for(int j=0;j<8;j++)
            #pragma unroll
            for(int q=0;q<4;q++) acc[i][j][q]=0.f;

    #define LOAD_STAGE(cc,buf) do{                                       \
        float* As_ = smc + (buf)*STAGE_WORDS;                             \
        float* Bs_ = As_ + A_WORDS;                                       \
        _Pragma("unroll")                                                 \
        for(int i=0;i<12;i++){                                            \
            int idx=t+i*256, ks=idx>>10, rem=idx&1023;                    \
            int r=rem>>5, f=rem&31;                                       \
            cpa16(As_+(ks*32+r)*ASW+f*4,                                  \
                  Ag+((size_t)(ks*128+(cc)*32+r))*256+f*4);               \
        }                                                                 \
        _Pragma("unroll")                                                 \
        for(int i=0;i<9;i++){                                             \
            int idx=t+i*256;                                              \
            if(idx<2112){                                                 \
                int r=idx/66, f=idx-r*66;                                 \
                cpa16(Bs_+r*BSW+f*4, Bg+((size_t)((cc)*32+r))*264+f*4);   \
            }                                                             \
        }                                                                 \
        CP_COMMIT();                                                      \
    }while(0)

    LOAD_STAGE(0,0);
    for(int st=0; st<4; st++){
        if(st==0) LOAD_STAGE(1,1);
        else if(st==1) LOAD_STAGE(2,0);
        else if(st==2) LOAD_STAGE(3,1);
        if(st<3){ CP_WAIT(1); } else { CP_WAIT(0); }
        __syncthreads();
        const uint32_t* Asu = (const uint32_t*)(smc + (st&1)*STAGE_WORDS);
        const uint32_t* Bsu = Asu + A_WORDS;
        #pragma unroll
        for(int ks=0; ks<3; ks++){
            #pragma unroll
            for(int kk=0; kk<4; kk++){
                int kr = ks*32 + kk*8 + tg;
                int kb = kk*8 + tg;
                uint32_t af[4][4];
                #pragma unroll
                for(int mi=0;mi<4;mi++){
                    int e = wm*64 + mi*16 + gg;
                    af[mi][0]=Asu[kr*ASW+e];     af[mi][1]=Asu[kr*ASW+e+8];
                    af[mi][2]=Asu[(kr+4)*ASW+e]; af[mi][3]=Asu[(kr+4)*ASW+e+8];
                }
                uint32_t bf[8][2];
                #pragma unroll
                for(int nj=0;nj<8;nj++){
                    int n = ks + wn*64 + nj*8 + gg;
                    bf[nj][0]=Bsu[kb*BSW+n]; bf[nj][1]=Bsu[(kb+4)*BSW+n];
                }
                #pragma unroll
                for(int mi=0;mi<4;mi++)
                    #pragma unroll
                    for(int nj=0;nj<8;nj++)
                        MMA_TF32(acc[mi][nj], af[mi], bf[nj]);
            }
        }
        __syncthreads();
    }

    float* red = smc;   // [128][4]
    #pragma unroll
    for(int mi=0;mi<4;mi++){
        float m0=-FLT_MAX, m1=-FLT_MAX;
        #pragma unroll
        for(int nj=0;nj<8;nj++){
            m0=fmaxf(m0,fmaxf(acc[mi][nj][0],acc[mi][nj][1]));
            m1=fmaxf(m1,fmaxf(acc[mi][nj][2],acc[mi][nj][3]));
        }
        m0=fmaxf(m0,__shfl_xor_sync(0xFFFFFFFFu,m0,1));
        m0=fmaxf(m0,__shfl_xor_sync(0xFFFFFFFFu,m0,2));
        m1=fmaxf(m1,__shfl_xor_sync(0xFFFFFFFFu,m1,1));
        m1=fmaxf(m1,__shfl_xor_sync(0xFFFFFFFFu,m1,2));
        if(tg==0){
            red[(wm*64+mi*16+gg)*4+wn]   = m0;
            red[(wm*64+mi*16+gg+8)*4+wn] = m1;
        }
    }
    __syncthreads();
    if(t<128){
        float v=fmaxf(fmaxf(red[t*4],red[t*4+1]),fmaxf(red[t*4+2],red[t*4+3]));
        g_cnn[(b*Sv+s)*Ev + e0 + t] = fmaxf(v + b2[s*256+e0+t], 0.f);
    }
}

// ---- layernorm (optional affine / dup-out / sq-norm-out) ----
__global__ __launch_bounds__(256) void layernorm_kernel(
    const float* __restrict__ in, const float* __restrict__ gw, const float* __restrict__ bw,
    float* __restrict__ out, float* __restrict__ out2, float* __restrict__ sqout)
{
    int row=blockIdx.x, t=threadIdx.x;
    float v=in[row*256+t];
    __shared__ float red[8];
    float su=warpSum(v);
    if((t&31)==0) red[t>>5]=su;
    __syncthreads();
    float tot=0.f;
    #pragma unroll
    for(int i=0;i<8;i++) tot+=red[i];
    float d=v - tot*(1.f/256.f);
    __syncthreads();
    float s2=warpSum(d*d);
    if((t&31)==0) red[t>>5]=s2;
    __syncthreads();
    float tot2=0.f;
    #pragma unroll
    for(int i=0;i<8;i++) tot2+=red[i];
    float y=d*rsqrtf(tot2*(1.f/256.f)+1e-5f);
    if(gw) y=y*gw[t]+bw[t];
    out[row*256+t]=y;
    if(out2) out2[row*256+t]=y;
    if(sqout){
        __syncthreads();
        float s3=warpSum(y*y);
        if((t&31)==0) red[t>>5]=s3;
        __syncthreads();
        if(t==0){
            float t3=0.f;
            #pragma unroll
            for(int i=0;i<8;i++) t3+=red[i];
            sqout[row]=t3;
        }
    }
}

// ---- tiled pairwise distance (Gram) + global max ----
__global__ __launch_bounds__(256) void dist_tile_kernel(const float* __restrict__ feat)
{
    __shared__ float Fi[16*65], Fj[16*65], redm[8];
    int t=threadIdx.x, bx=blockIdx.x;
    int b=bx>>4, it=(bx>>2)&3, jt=bx&3;
    int tn=t&15, tm=t>>4;
    float acc[4][4];
    #pragma unroll
    for(int i=0;i<4;i++)
        #pragma unroll
        for(int j=0;j<4;j++) acc[i][j]=0.f;
    for(int k0=0;k0<256;k0+=16){
        #pragma unroll
        for(int i=0;i<4;i++){
            int lin=t+i*256, am=lin>>4, ak=lin&15;
            Fi[ak*65+am]=feat[(size_t)(b*256+it*64+am)*256+k0+ak];
            Fj[ak*65+am]=feat[(size_t)(b*256+jt*64+am)*256+k0+ak];
        }
        __syncthreads();
        #pragma unroll
        for(int k=0;k<16;k++){
            float av[4],bv[4];
            #pragma unroll
            for(int j=0;j<4;j++){ av[j]=Fi[k*65+tm*4+j]; bv[j]=Fj[k*65+tn*4+j]; }
            #pragma unroll
            for(int i=0;i<4;i++)
                #pragma unroll
                for(int j=0;j<4;j++) acc[i][j]=fmaf(av[i],bv[j],acc[i][j]);
        }
        __syncthreads();
    }
    float lm=0.f;
    #pragma unroll
    for(int i=0;i<4;i++){
        int ii=it*64+tm*4+i; float sqi=g_sq[b*256+ii];
        #pragma unroll
        for(int j=0;j<4;j++){
            int jj=jt*64+tn*4+j;
            float dv=sqrtf(fmaxf(sqi+g_sq[b*256+jj]-2.f*acc[i][j],0.f));
            g_dist[((size_t)(b*256+ii))*256+jj]=dv;
            lm=fmaxf(lm,dv);
        }
    }
    lm=warpMax(lm);
    if((t&31)==0) redm[t>>5]=lm;
    __syncthreads();
    if(t==0){
        float mm=redm[0];
        #pragma unroll
        for(int p=1;p<8;p++) mm=fmaxf(mm,redm[p]);
        atomicMax(&g_dmax,__float_as_uint(mm));
    }
}

// ---- generic SGEMM (+bias,+residual,relu) ----
__global__ __launch_bounds__(256) void gemm_kernel(
    int M,int N,int K, const float* __restrict__ A, const float* __restrict__ Bm,
    const float* __restrict__ bias, const float* __restrict__ res, float* __restrict__ C, int relu)
{
    __shared__ float As[16][65], Bs[16][64];
    int t=threadIdx.x, tn=t&15, tm=t>>4;
    int n0=blockIdx.x<<6, m0=blockIdx.y<<6;
    float acc[4][4];
    #pragma unroll
    for(int i=0;i<4;i++)
        #pragma unroll
        for(int j=0;j<4;j++) acc[i][j]=0.f;
    for(int kk=0;kk<K;kk+=16){
        #pragma unroll
        for(int i=0;i<4;i++){
            int lin=t+i*256, am=lin>>4, ak=lin&15;
            As[ak][am]=A[(size_t)(m0+am)*K+kk+ak];
            int bn=lin&63, bk=lin>>6;
            Bs[bk][bn]=Bm[(size_t)(kk+bk)*N+n0+bn];
        }
        __syncthreads();
        #pragma unroll
        for(int k=0;k<16;k++){
            float av[4],bv[4];
            #pragma unroll
            for(int j=0;j<4;j++){ av[j]=As[k][tm*4+j]; bv[j]=Bs[k][tn*4+j]; }
            #pragma unroll
            for(int i=0;i<4;i++)
                #pragma unroll
                for(int j=0;j<4;j++) acc[i][j]=fmaf(av[i],bv[j],acc[i][j]);
        }
        __syncthreads();
    }
    #pragma unroll
    for(int i=0;i<4;i++){
        int mr=m0+tm*4+i;
        #pragma unroll
        for(int j=0;j<4;j++){
            int n=n0+tn*4+j;
            float v=acc[i][j];
            if(bias) v+=bias[n];
            if(res)  v+=res[(size_t)mr*N+n];
            if(relu) v=fmaxf(v,0.f);
            C[(size_t)mr*N+n]=v;
        }
    }
}

// ---- attention scores + bias + softmax ----
__global__ __launch_bounds__(256) void score_kernel(
    const float* __restrict__ q, const float* __restrict__ k,
    const float* __restrict__ bw, const float* __restrict__ bb)
{
    int blk=blockIdx.x, i=blk&255, bh=blk>>8, h=bh&7, b=bh>>3;
    int j=threadIdx.x;
    __shared__ float qs[32], red[8];
    if(j<32) qs[j]=q[((b*256+i)*8+h)*32+j];
    __syncthreads();
    const float4* q4=(const float4*)qs;
    const float4* k4=(const float4*)(k+((size_t)(b*256+j)*8+h)*32);
    float sc=0.f;
    #pragma unroll
    for(int p=0;p<8;p++){
        float4 a=q4[p], c=k4[p];
        sc=fmaf(a.x,c.x,sc); sc=fmaf(a.y,c.y,sc); sc=fmaf(a.z,c.z,sc); sc=fmaf(a.w,c.w,sc);
    }
    sc*=0.17677669529663687f;
    float dmax=__uint_as_float(g_dmax);
    float dn=g_dist[(size_t)(b*256+i)*256+j]/(dmax+1e-6f);
    float rd=fabsf((float)(i-j))*(1.0f/255.0f);
    sc += dn*bw[h] + rd*bw[8+h] + (1.f-rd)*bw[16+h] + (1.f-dn)*bw[24+h] + bb[h];
    float mx=warpMax(sc);
    if((j&31)==0) red[j>>5]=mx;
    __syncthreads();
    float bm=red[0];
    #pragma unroll
    for(int p=1;p<8;p++) bm=fmaxf(bm,red[p]);
    float e=expf(sc-bm);
    __syncthreads();
    float s=warpSum(e);
    if((j&31)==0) red[j>>5]=s;
    __syncthreads();
    float tot=0.f;
    #pragma unroll
    for(int p=0;p<8;p++) tot+=red[p];
    g_scores[(size_t)blk*256+j]=e/tot;
}

// ---- o = A @ V ----
__global__ __launch_bounds__(256) void av_kernel(const float* __restrict__ v)
{
    int bi=blockIdx.x, b=bi>>8, i=bi&255;
    int t=threadIdx.x, h=t>>5, d=t&31;
    __shared__ float as_[8*256];
    for(int idx=t; idx<2048; idx+=256){
        int hh=idx>>8, j=idx&255;
        as_[idx]=g_scores[((size_t)((b*8+hh)*256+i))*256+j];
    }
    __syncthreads();
    float acc=0.f;
    #pragma unroll 4
    for(int j=0;j<256;j++)
        acc=fmaf(as_[h*256+j], v[(size_t)(b*256+j)*256+h*32+d], acc);
    g_attno[(size_t)(b*256+i)*256+t]=acc;
}

__global__ __launch_bounds__(256) void pool_kernel()
{
    int blk=blockIdx.x, b=blk>>3, ns=blk&7, t=threadIdx.x;
    float mx=-FLT_MAX;
    #pragma unroll 4
    for(int si=0;si<32;si++)
        mx=fmaxf(mx,g_h[(size_t)(b*256+ns*32+si)*256+t]);
    g_pooled[b*2048+ns*256+t]=mx;
}

__global__ __launch_bounds__(256) void fc_kernel(
    const float* __restrict__ fw, const float* __restrict__ fb, float* __restrict__ out)
{
    int b=blockIdx.x, t=threadIdx.x;
    float a0=0.f,a1=0.f;
    for(int kk=t;kk<2048;kk+=256){
        float p=g_pooled[b*2048+kk];
        a0=fmaf(p,fw[kk*2+0],a0); a1=fmaf(p,fw[kk*2+1],a1);
    }
    __shared__ float r0[8],r1[8];
    a0=warpSum(a0); a1=warpSum(a1);
    if((t&31)==0){ r0[t>>5]=a0; r1[t>>5]=a1; }
    __syncthreads();
    if(t==0){
        float s0=0.f,s1=0.f;
        #pragma unroll
        for(int p=0;p<8;p++){ s0+=r0[p]; s1+=r1[p]; }
        out[b*2+0]=s0+fb[0]; out[b*2+1]=s1+fb[1];
    }
}

extern "C" void kernel_launch(void* const* d_in, const int* in_sizes, int n_in,
                              void* d_out, int out_size)
{
    const float* x=(const float*)d_in[0];
    const float* conv1_w=(const float*)d_in[1];
    const float* conv1_b=(const float*)d_in[2];
    const float* conv2_w=(const float*)d_in[3];
    const float* conv2_b=(const float*)d_in[4];
    const float* ln1_g=(const float*)d_in[5];
    const float* ln1_b=(const float*)d_in[6];
    const float* wq=(const float*)d_in[7];
    const float* bq=(const float*)d_in[8];
    const float* wk=(const float*)d_in[9];
    const float* bk=(const float*)d_in[10];
    const float* wv=(const float*)d_in[11];
    const float* bv=(const float*)d_in[12];
    const float* wo=(const float*)d_in[13];
    const float* bo=(const float*)d_in[14];
    const float* bias_w=(const float*)d_in[15];
    const float* bias_b=(const float*)d_in[16];
    const float* ln2_g=(const float*)d_in[17];
    const float* ln2_b=(const float*)d_in[18];
    const float* ffn_w1=(const float*)d_in[19];
    const float* ffn_b1=(const float*)d_in[20];
    const float* ffn_w2=(const float*)d_in[21];
    const float* ffn_b2=(const float*)d_in[22];
    const float* fc_w=(const float*)d_in[23];
    const float* fc_b=(const float*)d_in[24];
    float* out=(float*)d_out;

    float *p_cnn,*p_feat,*p_h,*p_hn,*p_q,*p_k,*p_v,*p_attno,*p_ffn,*p_sq;
    cudaGetSymbolAddress((void**)&p_cnn,g_cnn);
    cudaGetSymbolAddress((void**)&p_feat,g_feat);
    cudaGetSymbolAddress((void**)&p_h,g_h);
    cudaGetSymbolAddress((void**)&p_hn,g_hn);
    cudaGetSymbolAddress((void**)&p_q,g_q);
    cudaGetSymbolAddress((void**)&p_k,g_k);
    cudaGetSymbolAddress((void**)&p_v,g_v);
    cudaGetSymbolAddress((void**)&p_attno,g_attno);
    cudaGetSymbolAddress((void**)&p_ffn,g_ffn);
    cudaGetSymbolAddress((void**)&p_sq,g_sq);

    cudaFuncSetAttribute(conv2_mma_kernel,
                         cudaFuncAttributeMaxDynamicSharedMemorySize, CONV2_SMEM_BYTES);

    init_kernel<<<1,32>>>();
    conv1_kernel<<<2048,256>>>(x, conv1_w, conv1_b);
    w2t_kernel<<<4096,256>>>(conv2_w);
    conv2_mma_kernel<<<4096,256,CONV2_SMEM_BYTES>>>(conv2_b);
    layernorm_kernel<<<ROWS,256>>>(p_cnn, nullptr, nullptr, p_feat, p_h, p_sq);
    dist_tile_kernel<<<128,256>>>(p_feat);

    dim3 g256(4,32), g512(8,32);
    for(int l=0;l<2;l++){
        layernorm_kernel<<<ROWS,256>>>(p_h, ln1_g+l*256, ln1_b+l*256, p_hn, nullptr, nullptr);
        gemm_kernel<<<g256,256>>>(ROWS,256,256, p_hn, wq+l*65536, bq+l*256, nullptr, p_q, 0);
        gemm_kernel<<<g256,256>>>(ROWS,256,256, p_hn, wk+l*65536, bk+l*256, nullptr, p_k, 0);
        gemm_kernel<<<g256,256>>>(ROWS,256,256, p_hn, wv+l*65536, bv+l*256, nullptr, p_v, 0);
        score_kernel<<<Bv*Hv*Sv,256>>>(p_q, p_k, bias_w+l*32, bias_b+l*8);
        av_kernel<<<ROWS,256>>>(p_v);
        gemm_kernel<<<g256,256>>>(ROWS,256,256, p_attno, wo+l*65536, bo+l*256, p_h, p_h, 0);
        layernorm_kernel<<<ROWS,256>>>(p_h, ln2_g+l*256, ln2_b+l*256, p_hn, nullptr, nullptr);
        gemm_kernel<<<g512,256>>>(ROWS,512,256, p_hn, ffn_w1+l*131072, ffn_b1+l*512, nullptr, p_ffn, 1);
        gemm_kernel<<<g256,256>>>(ROWS,256,512, p_ffn, ffn_w2+l*131072, ffn_b2+l*256, p_h, p_h, 0);
    }
    pool_kernel<<<64,256>>>();
    fc_kernel<<<8,256>>>(fc_w, fc_b, out);
}

// round 5
// speedup vs baseline: 4.0812x; 1.3123x over previous
#include <cuda_runtime.h>
#include <math.h>
#include <cfloat>
#include <stdint.h>

#define Bv 8
#define Sv 256
#define Ev 256
#define Hv 8
#define ROWS (Bv*Sv)

__device__ float g_cnn[ROWS*Ev];
__device__ float g_feat[ROWS*Ev];
__device__ float g_h[ROWS*Ev];
__device__ float g_hn[ROWS*Ev];
__device__ float g_q[ROWS*Ev];
__device__ float g_k[ROWS*Ev];
__device__ float g_v[ROWS*Ev];
__device__ float g_attno[ROWS*Ev];
__device__ float g_ffn[ROWS*2*Ev];
__device__ float g_dist[Bv*Sv*Sv];
__device__ float g_pooled[Bv*8*Ev];
__device__ float g_sq[ROWS];
__device__ unsigned g_dmax;
__device__ float g_h1p[(size_t)2048*128*264];   // conv1 out, tf32, padded rows
__device__ float g_w2t[(size_t)256*384*256];    // w2 transposed, tf32

__device__ __forceinline__ float warpSum(float v){
    #pragma unroll
    for(int o=16;o>0;o>>=1) v += __shfl_xor_sync(0xFFFFFFFFu,v,o);
    return v;
}
__device__ __forceinline__ float warpMax(float v){
    #pragma unroll
    for(int o=16;o>0;o>>=1) v = fmaxf(v,__shfl_xor_sync(0xFFFFFFFFu,v,o));
    return v;
}
__device__ __forceinline__ float ftf32(float x){
    unsigned u; asm("cvt.rna.tf32.f32 %0, %1;" : "=r"(u) : "f"(x));
    return __uint_as_float(u);
}
__device__ __forceinline__ void cpa16(void* sm, const void* g){
    unsigned sa = (unsigned)__cvta_generic_to_shared(sm);
    asm volatile("cp.async.cg.shared.global [%0], [%1], 16;" :: "r"(sa), "l"(g));
}
#define CP_COMMIT() asm volatile("cp.async.commit_group;")
#define CP_WAIT(N)  asm volatile("cp.async.wait_group %0;" :: "n"(N))
#define MMA_TF32(C,A,B) \
    asm volatile("mma.sync.aligned.m16n8k8.row.col.f32.tf32.tf32.f32 " \
        "{%0,%1,%2,%3},{%4,%5,%6,%7},{%8,%9},{%0,%1,%2,%3};" \
        : "+f"((C)[0]),"+f"((C)[1]),"+f"((C)[2]),"+f"((C)[3]) \
        : "r"((A)[0]),"r"((A)[1]),"r"((A)[2]),"r"((A)[3]),"r"((B)[0]),"r"((B)[1]))

__global__ void init_kernel(){ if(threadIdx.x==0) g_dmax=0u; }

// ---- conv1 -> g_h1p (tf32, rows of 264 with zero pads at p=0 and p>=257) ----
__global__ __launch_bounds__(256) void conv1_kernel(
    const float* __restrict__ x, const float* __restrict__ w1, const float* __restrict__ b1)
{
    __shared__ float xs[4*258], w1s[1536], b1s[128];
    int t=threadIdx.x, sb=blockIdx.x, s=sb>>3, b=sb&7;
    for(int idx=t; idx<4*258; idx+=256){
        int ci=idx/258, p=idx-ci*258; float v=0.f;
        if(p>=1 && p<=256) v = x[((b*Sv+s)*4+ci)*256 + p-1];
        xs[idx]=v;
    }
    for(int idx=t; idx<1536; idx+=256) w1s[idx]=w1[s*1536+idx];
    if(t<128) b1s[t]=b1[s*128+t];
    __syncthreads();
    for(int idx=t; idx<128*256; idx+=256){
        int c=idx>>8, lp=idx&255;
        float a=b1s[c]; const float* wr=&w1s[c*12];
        #pragma unroll
        for(int ci=0;ci<4;ci++){
            const float* xr=&xs[ci*258+lp];
            a=fmaf(xr[0],wr[ci*3+0],a); a=fmaf(xr[1],wr[ci*3+1],a); a=fmaf(xr[2],wr[ci*3+2],a);
        }
        g_h1p[((size_t)sb*128+c)*264 + lp+1] = ftf32(fmaxf(a,0.f));
    }
    for(int idx=t; idx<128*8; idx+=256){
        int c=idx>>3, q=idx&7, p=(q==0)?0:(256+q);
        g_h1p[((size_t)sb*128+c)*264 + p]=0.f;
    }
}

// ---- w2 transpose: [s][e][c*3+k] -> g_w2t[s][k*128+c][e] (tf32) ----
__global__ __launch_bounds__(256) void w2t_kernel(const float* __restrict__ w2)
{
    __shared__ float tile[64*97];
    int t=threadIdx.x, bx=blockIdx.x;
    int s=bx>>4, et=(bx>>2)&3, kt=bx&3;
    for(int idx=t; idx<64*96; idx+=256){
        int e=idx/96, sc=idx-e*96;
        tile[e*97+sc] = w2[((size_t)(s*256+et*64+e))*384 + kt*96 + sc];
    }
    __syncthreads();
    for(int idx=t; idx<64*96; idx+=256){
        int sc=idx>>6, e=idx&63;
        int cd=sc/3, c=kt*32+cd, k=sc-cd*3;
        g_w2t[((size_t)(s*384+k*128+c))*256 + et*64+e] = ftf32(tile[e*97+sc]);
    }
}

// ---- conv2 as tf32 MMA GEMM (M=128 e, N=256 l, K=384) + maxpool epilogue ----
#define ASW 136
#define BSW 264
#define A_WORDS (96*ASW)
#define STAGE_WORDS (A_WORDS + 32*BSW)
#define CONV2_SMEM_BYTES (2*STAGE_WORDS*4)

__global__ __launch_bounds__(256,1) void conv2_mma_kernel(const float* __restrict__ b2)
{
    extern __shared__ float smc[];
    int t=threadIdx.x, bx=blockIdx.x;
    int s=bx>>4, eh=(bx>>3)&1, b=bx&7, sb=s*8+b;
    int lane=t&31, wid=t>>5, gg=lane>>2, tg=lane&3;
    int wm=wid&1, wn=wid>>1, e0=eh*128;
    const float* Ag = g_w2t + (size_t)s*384*256 + e0;
    const float* Bg = g_h1p + (size_t)sb*128*264;

    float acc[4][8][4];
    #pragma unroll
    for(int i=0;i<4;i++)
        #pragma unroll
        for(int j=0;j<8;j++)
            #pragma unroll
            for(int q=0;q<4;q++) acc[i][j][q]=0.f;

    #define LOAD_STAGE(cc,buf) do{                                       \
        float* As_ = smc + (buf)*STAGE_WORDS;                             \
        float* Bs_ = As_ + A_WORDS;                                       \
        _Pragma("unroll")                                                 \
        for(int i=0;i<12;i++){                                            \
            int idx=t+i*256, ks=idx>>10, rem=idx&1023;                    \
            int r=rem>>5, f=rem&31;                                       \
            cpa16(As_+(ks*32+r)*ASW+f*4,                                  \
                  Ag+((size_t)(ks*128+(cc)*32+r))*256+f*4);               \
        }                                                                 \
        _Pragma("unroll")                                                 \
        for(int i=0;i<9;i++){                                             \
            int idx=t+i*256;                                              \
            if(idx<2112){                                                 \
                int r=idx/66, f=idx-r*66;                                 \
                cpa16(Bs_+r*BSW+f*4, Bg+((size_t)((cc)*32+r))*264+f*4);   \
            }                                                             \
        }                                                                 \
        CP_COMMIT();                                                      \
    }while(0)

    LOAD_STAGE(0,0);
    for(int st=0; st<4; st++){
        if(st==0) LOAD_STAGE(1,1);
        else if(st==1) LOAD_STAGE(2,0);
        else if(st==2) LOAD_STAGE(3,1);
        if(st<3){ CP_WAIT(1); } else { CP_WAIT(0); }
        __syncthreads();
        const uint32_t* Asu = (const uint32_t*)(smc + (st&1)*STAGE_WORDS);
        const uint32_t* Bsu = Asu + A_WORDS;
        #pragma unroll
        for(int ks=0; ks<3; ks++){
            #pragma unroll
            for(int kk=0; kk<4; kk++){
                int kr = ks*32 + kk*8 + tg;
                int kb = kk*8 + tg;
                uint32_t af[4][4];
                #pragma unroll
                for(int mi=0;mi<4;mi++){
                    int e = wm*64 + mi*16 + gg;
                    af[mi][0]=Asu[kr*ASW+e];     af[mi][1]=Asu[kr*ASW+e+8];
                    af[mi][2]=Asu[(kr+4)*ASW+e]; af[mi][3]=Asu[(kr+4)*ASW+e+8];
                }
                uint32_t bf[8][2];
                #pragma unroll
                for(int nj=0;nj<8;nj++){
                    int n = ks + wn*64 + nj*8 + gg;
                    bf[nj][0]=Bsu[kb*BSW+n]; bf[nj][1]=Bsu[(kb+4)*BSW+n];
                }
                #pragma unroll
                for(int mi=0;mi<4;mi++)
                    #pragma unroll
                    for(int nj=0;nj<8;nj++)
                        MMA_TF32(acc[mi][nj], af[mi], bf[nj]);
            }
        }
        __syncthreads();
    }

    float* red = smc;   // [128][4]
    #pragma unroll
    for(int mi=0;mi<4;mi++){
        float m0=-FLT_MAX, m1=-FLT_MAX;
        #pragma unroll
        for(int nj=0;nj<8;nj++){
            m0=fmaxf(m0,fmaxf(acc[mi][nj][0],acc[mi][nj][1]));
            m1=fmaxf(m1,fmaxf(acc[mi][nj][2],acc[mi][nj][3]));
        }
        m0=fmaxf(m0,__shfl_xor_sync(0xFFFFFFFFu,m0,1));
        m0=fmaxf(m0,__shfl_xor_sync(0xFFFFFFFFu,m0,2));
        m1=fmaxf(m1,__shfl_xor_sync(0xFFFFFFFFu,m1,1));
        m1=fmaxf(m1,__shfl_xor_sync(0xFFFFFFFFu,m1,2));
        if(tg==0){
            red[(wm*64+mi*16+gg)*4+wn]   = m0;
            red[(wm*64+mi*16+gg+8)*4+wn] = m1;
        }
    }
    __syncthreads();
    if(t<128){
        float v=fmaxf(fmaxf(red[t*4],red[t*4+1]),fmaxf(red[t*4+2],red[t*4+3]));
        g_cnn[(b*Sv+s)*Ev + e0 + t] = fmaxf(v + b2[s*256+e0+t], 0.f);
    }
}

// ---- layernorm (optional affine / dup-out / sq-norm-out) ----
__global__ __launch_bounds__(256) void layernorm_kernel(
    const float* __restrict__ in, const float* __restrict__ gw, const float* __restrict__ bw,
    float* __restrict__ out, float* __restrict__ out2, float* __restrict__ sqout)
{
    int row=blockIdx.x, t=threadIdx.x;
    float v=in[row*256+t];
    __shared__ float red[8];
    float su=warpSum(v);
    if((t&31)==0) red[t>>5]=su;
    __syncthreads();
    float tot=0.f;
    #pragma unroll
    for(int i=0;i<8;i++) tot+=red[i];
    float d=v - tot*(1.f/256.f);
    __syncthreads();
    float s2=warpSum(d*d);
    if((t&31)==0) red[t>>5]=s2;
    __syncthreads();
    float tot2=0.f;
    #pragma unroll
    for(int i=0;i<8;i++) tot2+=red[i];
    float y=d*rsqrtf(tot2*(1.f/256.f)+1e-5f);
    if(gw) y=y*gw[t]+bw[t];
    out[row*256+t]=y;
    if(out2) out2[row*256+t]=y;
    if(sqout){
        __syncthreads();
        float s3=warpSum(y*y);
        if((t&31)==0) red[t>>5]=s3;
        __syncthreads();
        if(t==0){
            float t3=0.f;
            #pragma unroll
            for(int i=0;i<8;i++) t3+=red[i];
            sqout[row]=t3;
        }
    }
}

// ---- tiled pairwise distance (Gram) + global max ----
__global__ __launch_bounds__(256) void dist_tile_kernel(const float* __restrict__ feat)
{
    __shared__ float Fi[16*65], Fj[16*65], redm[8];
    int t=threadIdx.x, bx=blockIdx.x;
    int b=bx>>4, it=(bx>>2)&3, jt=bx&3;
    int tn=t&15, tm=t>>4;
    float acc[4][4];
    #pragma unroll
    for(int i=0;i<4;i++)
        #pragma unroll
        for(int j=0;j<4;j++) acc[i][j]=0.f;
    for(int k0=0;k0<256;k0+=16){
        #pragma unroll
        for(int i=0;i<4;i++){
            int lin=t+i*256, am=lin>>4, ak=lin&15;
            Fi[ak*65+am]=feat[(size_t)(b*256+it*64+am)*256+k0+ak];
            Fj[ak*65+am]=feat[(size_t)(b*256+jt*64+am)*256+k0+ak];
        }
        __syncthreads();
        #pragma unroll
        for(int k=0;k<16;k++){
            float av[4],bv[4];
            #pragma unroll
            for(int j=0;j<4;j++){ av[j]=Fi[k*65+tm*4+j]; bv[j]=Fj[k*65+tn*4+j]; }
            #pragma unroll
            for(int i=0;i<4;i++)
                #pragma unroll
                for(int j=0;j<4;j++) acc[i][j]=fmaf(av[i],bv[j],acc[i][j]);
        }
        __syncthreads();
    }
    float lm=0.f;
    #pragma unroll
    for(int i=0;i<4;i++){
        int ii=it*64+tm*4+i; float sqi=g_sq[b*256+ii];
        #pragma unroll
        for(int j=0;j<4;j++){
            int jj=jt*64+tn*4+j;
            float dv=sqrtf(fmaxf(sqi+g_sq[b*256+jj]-2.f*acc[i][j],0.f));
            g_dist[((size_t)(b*256+ii))*256+jj]=dv;
            lm=fmaxf(lm,dv);
        }
    }
    lm=warpMax(lm);
    if((t&31)==0) redm[t>>5]=lm;
    __syncthreads();
    if(t==0){
        float mm=redm[0];
        #pragma unroll
        for(int p=1;p<8;p++) mm=fmaxf(mm,redm[p]);
        atomicMax(&g_dmax,__float_as_uint(mm));
    }
}

// ---- 64x64 SGEMM tile body (float4 smem reads) ----
__device__ __forceinline__ void gemm64_tile(
    int N, int K, const float* __restrict__ A, const float* __restrict__ Bm,
    const float* __restrict__ bias, const float* __restrict__ res,
    float* __restrict__ C, int relu, int m0, int n0,
    float* As, float* Bs)   // As,Bs: [16][68]
{
    int t=threadIdx.x, tn=t&15, tm=t>>4;
    float acc[4][4];
    #pragma unroll
    for(int i=0;i<4;i++)
        #pragma unroll
        for(int j=0;j<4;j++) acc[i][j]=0.f;
    for(int kk=0;kk<K;kk+=16){
        #pragma unroll
        for(int i=0;i<4;i++){
            int lin=t+i*256, am=lin>>4, ak=lin&15;
            As[ak*68+am]=A[(size_t)(m0+am)*K+kk+ak];
            int bn=lin&63, bk=lin>>6;
            Bs[bk*68+bn]=Bm[(size_t)(kk+bk)*N+n0+bn];
        }
        __syncthreads();
        #pragma unroll
        for(int k=0;k<16;k++){
            float4 a4=*(const float4*)(As+k*68+tm*4);
            float4 b4=*(const float4*)(Bs+k*68+tn*4);
            float av[4]={a4.x,a4.y,a4.z,a4.w}, bv[4]={b4.x,b4.y,b4.z,b4.w};
            #pragma unroll
            for(int i=0;i<4;i++)
                #pragma unroll
                for(int j=0;j<4;j++) acc[i][j]=fmaf(av[i],bv[j],acc[i][j]);
        }
        __syncthreads();
    }
    #pragma unroll
    for(int i=0;i<4;i++){
        int mr=m0+tm*4+i;
        #pragma unroll
        for(int j=0;j<4;j++){
            int n=n0+tn*4+j;
            float v=acc[i][j];
            if(bias) v+=bias[n];
            if(res)  v+=res[(size_t)mr*N+n];
            if(relu) v=fmaxf(v,0.f);
            C[(size_t)mr*N+n]=v;
        }
    }
}

__global__ __launch_bounds__(256) void gemm_kernel(
    int N,int K, const float* __restrict__ A, const float* __restrict__ Bm,
    const float* __restrict__ bias, const float* __restrict__ res,
    float* __restrict__ C, int relu)
{
    __shared__ float As[16*68], Bs[16*68];
    gemm64_tile(N,K,A,Bm,bias,res,C,relu, blockIdx.y<<6, blockIdx.x<<6, As, Bs);
}

// fused q/k/v projections: blockIdx.z selects weight/bias/output
__global__ __launch_bounds__(256) void qkv_kernel(
    const float* __restrict__ A,
    const float* __restrict__ wq, const float* __restrict__ wk, const float* __restrict__ wv,
    const float* __restrict__ bq, const float* __restrict__ bk, const float* __restrict__ bv)
{
    __shared__ float As[16*68], Bs[16*68];
    int z=blockIdx.z;
    const float* Bm = (z==0)? wq : (z==1)? wk : wv;
    const float* bias = (z==0)? bq : (z==1)? bk : bv;
    float* C = (z==0)? g_q : (z==1)? g_k : g_v;
    gemm64_tile(256,256,A,Bm,bias,nullptr,C,0, blockIdx.y<<6, blockIdx.x<<6, As, Bs);
}

// ---- fused attention: scores + bias + softmax + AV, per (b,h,64-row tile) ----
#define ATT_SMEM ((64*36 + 256*36 + 256*36)*4)
__global__ __launch_bounds__(256) void attn_kernel(
    const float* __restrict__ q, const float* __restrict__ k, const float* __restrict__ v,
    const float* __restrict__ bw, const float* __restrict__ bb)
{
    extern __shared__ float sa[];
    float* qs = sa;             // [64][36]
    float* ks = sa + 64*36;     // [256][36]
    float* vs = ks + 256*36;    // [256][36]
    int t=threadIdx.x, bx=blockIdx.x;
    int b=bx>>5, h=(bx>>2)&7, it=bx&3;
    int ti=t>>2, tj=t&3;
    int i=it*64+ti;

    for(int idx=t; idx<2048; idx+=256){
        int j=idx>>3, dc=idx&7;
        *(float4*)(ks + j*36 + dc*4) = *(const float4*)(k + (size_t)(b*256+j)*256 + h*32 + dc*4);
        *(float4*)(vs + j*36 + dc*4) = *(const float4*)(v + (size_t)(b*256+j)*256 + h*32 + dc*4);
    }
    for(int idx=t; idx<512; idx+=256){
        int r=idx>>3, dc=idx&7;
        *(float4*)(qs + r*36 + dc*4) = *(const float4*)(q + (size_t)(b*256+it*64+r)*256 + h*32 + dc*4);
    }
    __syncthreads();

    float qr[32];
    #pragma unroll
    for(int p=0;p<8;p++){
        float4 qv=*(const float4*)(qs + ti*36 + p*4);
        qr[p*4]=qv.x; qr[p*4+1]=qv.y; qr[p*4+2]=qv.z; qr[p*4+3]=qv.w;
    }

    float dmax=__uint_as_float(g_dmax);
    float inv=1.f/(dmax+1e-6f);
    float b0=bw[h], b1=bw[8+h], b2=bw[16+h], b3=bw[24+h];
    float ca=inv*(b0-b3);
    float cb=(b1-b2)*(1.f/255.f);
    float cst=b2+b3+bb[h];
    const float* drow = g_dist + ((size_t)(b*256+i))*256;

    float s[64];
    float mx=-FLT_MAX;
    #pragma unroll 4
    for(int jj=0;jj<64;jj++){
        int j=jj*4+tj;
        float sc=0.f;
        const float* kr=ks+j*36;
        #pragma unroll
        for(int p=0;p<8;p++){
            float4 kv=*(const float4*)(kr+p*4);
            sc=fmaf(qr[p*4],kv.x,sc);   sc=fmaf(qr[p*4+1],kv.y,sc);
            sc=fmaf(qr[p*4+2],kv.z,sc); sc=fmaf(qr[p*4+3],kv.w,sc);
        }
        sc*=0.17677669529663687f;
        sc += drow[j]*ca + fabsf((float)(i-j))*cb + cst;
        s[jj]=sc;
        mx=fmaxf(mx,sc);
    }
    mx=fmaxf(mx,__shfl_xor_sync(0xFFFFFFFFu,mx,1));
    mx=fmaxf(mx,__shfl_xor_sync(0xFFFFFFFFu,mx,2));
    float sum=0.f;
    #pragma unroll
    for(int jj=0;jj<64;jj++){ s[jj]=expf(s[jj]-mx); sum+=s[jj]; }
    sum+=__shfl_xor_sync(0xFFFFFFFFu,sum,1);
    sum+=__shfl_xor_sync(0xFFFFFFFFu,sum,2);
    float rs=1.f/sum;

    float o[32];
    #pragma unroll
    for(int d=0;d<32;d++) o[d]=0.f;
    #pragma unroll 4
    for(int jj=0;jj<64;jj++){
        float sv=s[jj]*rs;
        const float* vr=vs+(jj*4+tj)*36;
        #pragma unroll
        for(int p=0;p<8;p++){
            float4 vv=*(const float4*)(vr+p*4);
            o[p*4]  =fmaf(sv,vv.x,o[p*4]);   o[p*4+1]=fmaf(sv,vv.y,o[p*4+1]);
            o[p*4+2]=fmaf(sv,vv.z,o[p*4+2]); o[p*4+3]=fmaf(sv,vv.w,o[p*4+3]);
        }
    }
    #pragma unroll
    for(int d=0;d<32;d++){
        o[d]+=__shfl_xor_sync(0xFFFFFFFFu,o[d],1);
        o[d]+=__shfl_xor_sync(0xFFFFFFFFu,o[d],2);
    }
    if(tj==0){
        float* orow = g_attno + (size_t)(b*256+i)*256 + h*32;
        #pragma unroll
        for(int p=0;p<8;p++)
            *(float4*)(orow+p*4) = make_float4(o[p*4],o[p*4+1],o[p*4+2],o[p*4+3]);
    }
}

__global__ __launch_bounds__(256) void pool_kernel()
{
    int blk=blockIdx.x, b=blk>>3, ns=blk&7, t=threadIdx.x;
    float mx=-FLT_MAX;
    #pragma unroll 4
    for(int si=0;si<32;si++)
        mx=fmaxf(mx,g_h[(size_t)(b*256+ns*32+si)*256+t]);
    g_pooled[b*2048+ns*256+t]=mx;
}

__global__ __launch_bounds__(256) void fc_kernel(
    const float* __restrict__ fw, const float* __restrict__ fb, float* __restrict__ out)
{
    int b=blockIdx.x, t=threadIdx.x;
    float a0=0.f,a1=0.f;
    for(int kk=t;kk<2048;kk+=256){
        float p=g_pooled[b*2048+kk];
        a0=fmaf(p,fw[kk*2+0],a0); a1=fmaf(p,fw[kk*2+1],a1);
    }
    __shared__ float r0[8],r1[8];
    a0=warpSum(a0); a1=warpSum(a1);
    if((t&31)==0){ r0[t>>5]=a0; r1[t>>5]=a1; }
    __syncthreads();
    if(t==0){
        float s0=0.f,s1=0.f;
        #pragma unroll
        for(int p=0;p<8;p++){ s0+=r0[p]; s1+=r1[p]; }
        out[b*2+0]=s0+fb[0]; out[b*2+1]=s1+fb[1];
    }
}

extern "C" void kernel_launch(void* const* d_in, const int* in_sizes, int n_in,
                              void* d_out, int out_size)
{
    const float* x=(const float*)d_in[0];
    const float* conv1_w=(const float*)d_in[1];
    const float* conv1_b=(const float*)d_in[2];
    const float* conv2_w=(const float*)d_in[3];
    const float* conv2_b=(const float*)d_in[4];
    const float* ln1_g=(const float*)d_in[5];
    const float* ln1_b=(const float*)d_in[6];
    const float* wq=(const float*)d_in[7];
    const float* bq=(const float*)d_in[8];
    const float* wk=(const float*)d_in[9];
    const float* bk=(const float*)d_in[10];
    const float* wv=(const float*)d_in[11];
    const float* bv=(const float*)d_in[12];
    const float* wo=(const float*)d_in[13];
    const float* bo=(const float*)d_in[14];
    const float* bias_w=(const float*)d_in[15];
    const float* bias_b=(const float*)d_in[16];
    const float* ln2_g=(const float*)d_in[17];
    const float* ln2_b=(const float*)d_in[18];
    const float* ffn_w1=(const float*)d_in[19];
    const float* ffn_b1=(const float*)d_in[20];
    const float* ffn_w2=(const float*)d_in[21];
    const float* ffn_b2=(const float*)d_in[22];
    const float* fc_w=(const float*)d_in[23];
    const float* fc_b=(const float*)d_in[24];
    float* out=(float*)d_out;

    float *p_cnn,*p_feat,*p_h,*p_hn,*p_q,*p_k,*p_v,*p_attno,*p_ffn,*p_sq;
    cudaGetSymbolAddress((void**)&p_cnn,g_cnn);
    cudaGetSymbolAddress((void**)&p_feat,g_feat);
    cudaGetSymbolAddress((void**)&p_h,g_h);
    cudaGetSymbolAddress((void**)&p_hn,g_hn);
    cudaGetSymbolAddress((void**)&p_q,g_q);
    cudaGetSymbolAddress((void**)&p_k,g_k);
    cudaGetSymbolAddress((void**)&p_v,g_v);
    cudaGetSymbolAddress((void**)&p_attno,g_attno);
    cudaGetSymbolAddress((void**)&p_ffn,g_ffn);
    cudaGetSymbolAddress((void**)&p_sq,g_sq);

    cudaFuncSetAttribute(conv2_mma_kernel,
                         cudaFuncAttributeMaxDynamicSharedMemorySize, CONV2_SMEM_BYTES);
    cudaFuncSetAttribute(attn_kernel,
                         cudaFuncAttributeMaxDynamicSharedMemorySize, ATT_SMEM);

    init_kernel<<<1,32>>>();
    conv1_kernel<<<2048,256>>>(x, conv1_w, conv1_b);
    w2t_kernel<<<4096,256>>>(conv2_w);
    conv2_mma_kernel<<<4096,256,CONV2_SMEM_BYTES>>>(conv2_b);
    layernorm_kernel<<<ROWS,256>>>(p_cnn, nullptr, nullptr, p_feat, p_h, p_sq);
    dist_tile_kernel<<<128,256>>>(p_feat);

    dim3 g256(4,32), g512(8,32), gqkv(4,32,3);
    for(int l=0;l<2;l++){
        layernorm_kernel<<<ROWS,256>>>(p_h, ln1_g+l*256, ln1_b+l*256, p_hn, nullptr, nullptr);
        qkv_kernel<<<gqkv,256>>>(p_hn, wq+l*65536, wk+l*65536, wv+l*65536,
                                 bq+l*256, bk+l*256, bv+l*256);
        attn_kernel<<<256,256,ATT_SMEM>>>(p_q, p_k, p_v, bias_w+l*32, bias_b+l*8);
        gemm_kernel<<<g256,256>>>(256,256, p_attno, wo+l*65536, bo+l*256, p_h, p_h, 0);
        layernorm_kernel<<<ROWS,256>>>(p_h, ln2_g+l*256, ln2_b+l*256, p_hn, nullptr, nullptr);
        gemm_kernel<<<g512,256>>>(512,256, p_hn, ffn_w1+l*131072, ffn_b1+l*512, nullptr, p_ffn, 1);
        gemm_kernel<<<g256,256>>>(256,512, p_ffn, ffn_w2+l*131072, ffn_b2+l*256, p_h, p_h, 0);
    }
    pool_kernel<<<64,256>>>();
    fc_kernel<<<8,256>>>(fc_w, fc_b, out);
}